// round 1
// baseline (speedup 1.0000x reference)
#include <cuda_runtime.h>

#define NUM_CAMS 6
#define C_FEAT   64
#define HF       16
#define WF       44
#define P_TOTAL  (8 * 128 * 128)   // 131072
#define FEAT_ELEMS (NUM_CAMS * C_FEAT * HF * WF)  // 270336

// Precomputed per-camera projection (rows 0..2 of cam2img @ ego2cam)
__device__ float g_proj[NUM_CAMS][12];
// NHWC-transposed features: [cam][y][x][c], c contiguous
__device__ float g_feat_t[NUM_CAMS * HF * WF * C_FEAT];

// ---------------------------------------------------------------------------
// Kernel 1: proj[n] = cam2img[n] @ ego2cam[n]  (rows 0..2 only)
// ---------------------------------------------------------------------------
__global__ void proj_kernel(const float* __restrict__ ego2cam,
                            const float* __restrict__ cam2img) {
    int t = threadIdx.x;                // 0..71
    if (t >= NUM_CAMS * 12) return;
    int n = t / 12;
    int r = (t % 12) / 4;
    int c = t % 4;
    float s = 0.f;
    #pragma unroll
    for (int k = 0; k < 4; k++)
        s += cam2img[n * 16 + r * 4 + k] * ego2cam[n * 16 + k * 4 + c];
    g_proj[n][r * 4 + c] = s;
}

// ---------------------------------------------------------------------------
// Kernel 2: transpose (n,c,y,x) -> (n,y,x,c)
// ---------------------------------------------------------------------------
__global__ void transpose_kernel(const float* __restrict__ in) {
    int idx = blockIdx.x * blockDim.x + threadIdx.x;
    if (idx >= FEAT_ELEMS) return;
    int x = idx % WF;
    int t = idx / WF;
    int y = t % HF;  t /= HF;
    int c = t % C_FEAT;
    int n = t / C_FEAT;
    g_feat_t[(((n * HF + y) * WF) + x) * C_FEAT + c] = in[idx];
}

// ---------------------------------------------------------------------------
// Kernel 3: project + bilinear sample + fuse. One thread per voxel point,
// all 64 channels accumulated in registers.
// ---------------------------------------------------------------------------
__global__ void __launch_bounds__(256)
fuse_kernel(const float* __restrict__ vox, float* __restrict__ out) {
    int p = blockIdx.x * blockDim.x + threadIdx.x;   // grid sized exactly

    float px = vox[p];
    float py = vox[P_TOTAL + p];
    float pz = vox[2 * P_TOTAL + p];

    float4 acc[16];
    #pragma unroll
    for (int i = 0; i < 16; i++) acc[i] = make_float4(0.f, 0.f, 0.f, 0.f);

    int nvalid = 0;

    for (int n = 0; n < NUM_CAMS; n++) {
        const float* M = g_proj[n];
        float uu = M[0] * px + M[1] * py + M[2]  * pz + M[3];
        float vv = M[4] * px + M[5] * py + M[6]  * pz + M[7];
        float dd = M[8] * px + M[9] * py + M[10] * pz + M[11];

        float inv = 1.0f / (dd + 1e-6f);
        float u = uu * inv;
        float v = vv * inv;

        bool valid = (dd > 0.1f) && (u >= 0.f) && (u <= 703.f)
                                 && (v >= 0.f) && (v <= 255.f);
        nvalid += valid ? 1 : 0;

        if (!__any_sync(0xffffffffu, valid)) continue;

        // feature-map coords (align_corners=True roundtrip == u/stride)
        float x = u * (1.0f / 16.0f);
        float y = v * (1.0f / 16.0f);
        float x0f = floorf(x);
        float y0f = floorf(y);
        float wx1 = x - x0f, wy1 = y - y0f;
        float wx0 = 1.f - wx1, wy0 = 1.f - wy1;
        int x0 = (int)x0f;
        int y0 = (int)y0f;

        int dx_off = C_FEAT;
        int dy_off = WF * C_FEAT;
        if (x0 + 1 >= WF) { wx1 = 0.f; dx_off = 0; }
        if (y0 + 1 >= HF) { wy1 = 0.f; dy_off = 0; }

        float w00 = wx0 * wy0;
        float w01 = wx1 * wy0;
        float w10 = wx0 * wy1;
        float w11 = wx1 * wy1;

        int base = ((n * HF + y0) * WF + x0) * C_FEAT;
        if (!valid) {            // dead lane: weight 0, safe broadcast address
            w00 = w01 = w10 = w11 = 0.f;
            base = 0; dx_off = 0; dy_off = 0;
        }

        const float4* f00 = (const float4*)(g_feat_t + base);
        const float4* f01 = (const float4*)(g_feat_t + base + dx_off);
        const float4* f10 = (const float4*)(g_feat_t + base + dy_off);
        const float4* f11 = (const float4*)(g_feat_t + base + dy_off + dx_off);

        #pragma unroll
        for (int i = 0; i < 16; i++) {
            float4 a = f00[i];
            float4 b = f01[i];
            float4 g = f10[i];
            float4 h = f11[i];
            acc[i].x = fmaf(w00, a.x, fmaf(w01, b.x, fmaf(w10, g.x, fmaf(w11, h.x, acc[i].x))));
            acc[i].y = fmaf(w00, a.y, fmaf(w01, b.y, fmaf(w10, g.y, fmaf(w11, h.y, acc[i].y))));
            acc[i].z = fmaf(w00, a.z, fmaf(w01, b.z, fmaf(w10, g.z, fmaf(w11, h.z, acc[i].z))));
            acc[i].w = fmaf(w00, a.w, fmaf(w01, b.w, fmaf(w10, g.w, fmaf(w11, h.w, acc[i].w))));
        }
    }

    float rden = 1.0f / fmaxf((float)nvalid, 1.0f);

    float* op = out + p;
    #pragma unroll
    for (int i = 0; i < 16; i++) {
        op[(4 * i + 0) * P_TOTAL] = acc[i].x * rden;
        op[(4 * i + 1) * P_TOTAL] = acc[i].y * rden;
        op[(4 * i + 2) * P_TOTAL] = acc[i].z * rden;
        op[(4 * i + 3) * P_TOTAL] = acc[i].w * rden;
    }
}

// ---------------------------------------------------------------------------
extern "C" void kernel_launch(void* const* d_in, const int* in_sizes, int n_in,
                              void* d_out, int out_size) {
    const float* img_feats = (const float*)d_in[0];   // (6,64,16,44)
    const float* ego2cam   = (const float*)d_in[1];   // (6,4,4)
    const float* cam2img   = (const float*)d_in[2];   // (6,4,4)
    const float* vox       = (const float*)d_in[3];   // (3,8,128,128)
    float* out = (float*)d_out;                       // (1,64,8,128,128)

    proj_kernel<<<1, 128>>>(ego2cam, cam2img);
    transpose_kernel<<<(FEAT_ELEMS + 255) / 256, 256>>>(img_feats);
    fuse_kernel<<<P_TOTAL / 256, 256>>>(vox, out);
}